// round 6
// baseline (speedup 1.0000x reference)
#include <cuda_runtime.h>

// Problem: B=4096, D=128. out[4096][16384] fp32.
// part1 (cols 0..8191)  = softmax([a@b.T , a@a.T - diag*INF]) rows
// part2 (cols 8192..)   = softmax([b@a.T , b@b.T - diag*INF]) rows
// No max subtraction needed: logits in [-10,10].

#define NROWS 4096
#define DDIM  128
#define OCOLS 16384

__device__ float g_a[NROWS * DDIM];
__device__ float g_b[NROWS * DDIM];
__device__ float g_sums[2 * NROWS];   // [0..4095]=part1 row sums, [4096..]=part2

// ---------------- normalize + zero sums ----------------
__global__ void norm_kernel(const float* __restrict__ z1,
                            const float* __restrict__ z2) {
    int row = blockIdx.x;           // 0..8191
    int tid = threadIdx.x;          // 0..127
    const float* src; float* dst; int r;
    if (row < NROWS) { src = z1; dst = g_a; r = row; }
    else             { src = z2; dst = g_b; r = row - NROWS; }
    float v = src[r * DDIM + tid];
    float s = v * v;
    #pragma unroll
    for (int o = 16; o; o >>= 1) s += __shfl_xor_sync(0xffffffffu, s, o);
    __shared__ float ws[4];
    if ((tid & 31) == 0) ws[tid >> 5] = s;
    __syncthreads();
    float tot = ws[0] + ws[1] + ws[2] + ws[3];
    float rs = rsqrtf(fmaxf(tot, 1e-12f));
    dst[r * DDIM + tid] = v * rs;
    if (tid == 0) g_sums[row] = 0.0f;
}

// ---------------- fused GEMM + exp + rowsum ----------------
// Tile 128x128, K chunked by 32. 256 threads, 8x8 per thread.
// Packed f32x2 FMA (Blackwell) for the inner product.

#define BK  32
#define LDT 130   // padded stride for [k][m] transposed tiles (float2-aligned, conflict-free LDS.64)

__device__ __forceinline__ unsigned long long pk2(float x) {
    unsigned long long r;
    asm("mov.b64 %0, {%1,%1};" : "=l"(r) : "f"(x));
    return r;
}
__device__ __forceinline__ void fma2(unsigned long long& d,
                                     unsigned long long a,
                                     unsigned long long b) {
    asm("fma.rn.f32x2 %0, %1, %2, %0;" : "+l"(d) : "l"(a), "l"(b));
}
__device__ __forceinline__ float2 upk(unsigned long long v) {
    float2 r;
    asm("mov.b64 {%0,%1}, %2;" : "=f"(r.x), "=f"(r.y) : "l"(v));
    return r;
}

__global__ void __launch_bounds__(256, 2)
gemm_exp_kernel(float* __restrict__ out) {
    __shared__ float As[BK * LDT];
    __shared__ float Bs[BK * LDT];
    __shared__ float rs_s[128];
    __shared__ float cs_s[128];

    // ---- job decode: 1024 AB tiles, 528 AA (ti<=tj), 528 BB (ti<=tj) ----
    int bi = blockIdx.x;
    int jobType, ti, tj;
    if (bi < 1024) {
        jobType = 0; ti = bi >> 5; tj = bi & 31;
    } else {
        int t = bi - 1024;
        jobType = (t < 528) ? 1 : 2;
        int tt = (t < 528) ? t : t - 528;
        int i = 0;
        while (tt >= 32 - i) { tt -= 32 - i; i++; }
        ti = i; tj = i + tt;
    }
    const float* L = (jobType == 2) ? g_b : g_a;
    const float* R = (jobType == 1) ? g_a : g_b;
    const float* Ag = L + ti * 128 * DDIM;
    const float* Bg = R + tj * 128 * DDIM;

    int tid = threadIdx.x;
    int tx = tid & 15, ty = tid >> 4;   // 16 x 16
    int r0 = ty * 8, c0 = tx * 8;

    if (tid < 128) { rs_s[tid] = 0.0f; cs_s[tid] = 0.0f; }

    unsigned long long acc[8][4];
    #pragma unroll
    for (int i = 0; i < 8; i++)
        #pragma unroll
        for (int j = 0; j < 4; j++) acc[i][j] = 0ull;

    for (int kc = 0; kc < DDIM; kc += BK) {
        __syncthreads();
        // load 128 rows x 32 k of each tile, store transposed [k][m]
        #pragma unroll
        for (int i = 0; i < 4; i++) {
            int f  = tid + i * 256;          // 0..1023 float4 slots
            int m  = f >> 3;                 // row 0..127
            int k4 = f & 7;                  // f4 within chunk
            float4 va = *reinterpret_cast<const float4*>(Ag + m * DDIM + kc + k4 * 4);
            float4 vb = *reinterpret_cast<const float4*>(Bg + m * DDIM + kc + k4 * 4);
            int kb = k4 * 4;
            As[(kb + 0) * LDT + m] = va.x;
            As[(kb + 1) * LDT + m] = va.y;
            As[(kb + 2) * LDT + m] = va.z;
            As[(kb + 3) * LDT + m] = va.w;
            Bs[(kb + 0) * LDT + m] = vb.x;
            Bs[(kb + 1) * LDT + m] = vb.y;
            Bs[(kb + 2) * LDT + m] = vb.z;
            Bs[(kb + 3) * LDT + m] = vb.w;
        }
        __syncthreads();
        #pragma unroll
        for (int k = 0; k < BK; k++) {
            const float2* ap = reinterpret_cast<const float2*>(&As[k * LDT + r0]);
            const unsigned long long* bp =
                reinterpret_cast<const unsigned long long*>(&Bs[k * LDT + c0]);
            float2 a0 = ap[0], a1 = ap[1], a2 = ap[2], a3 = ap[3];
            unsigned long long b0 = bp[0], b1 = bp[1], b2 = bp[2], b3 = bp[3];
            unsigned long long av[8] = {pk2(a0.x), pk2(a0.y), pk2(a1.x), pk2(a1.y),
                                        pk2(a2.x), pk2(a2.y), pk2(a3.x), pk2(a3.y)};
            #pragma unroll
            for (int i = 0; i < 8; i++) {
                fma2(acc[i][0], av[i], b0);
                fma2(acc[i][1], av[i], b1);
                fma2(acc[i][2], av[i], b2);
                fma2(acc[i][3], av[i], b3);
            }
        }
    }

    // ---- epilogue: exp, diag mask, primary + transposed writes, rowsums ----
    float ev[8][8];
    #pragma unroll
    for (int i = 0; i < 8; i++)
        #pragma unroll
        for (int j4 = 0; j4 < 4; j4++) {
            float2 p = upk(acc[i][j4]);
            ev[i][j4 * 2 + 0] = __expf(p.x * 10.0f);
            ev[i][j4 * 2 + 1] = __expf(p.y * 10.0f);
        }

    if (jobType != 0 && ti == tj) {
        // diagonal of aa/bb masked to exactly 0 (exp(-1e9) == 0 in fp32)
        #pragma unroll
        for (int i = 0; i < 8; i++)
            #pragma unroll
            for (int j = 0; j < 8; j++)
                if (r0 + i == c0 + j) ev[i][j] = 0.0f;
    }

    int colP = (jobType == 0) ? 0 : (jobType == 1 ? 4096 : 12288);
    int colT = (jobType == 0) ? 8192 : colP;
    bool doT = (jobType == 0) || (ti != tj);

    #pragma unroll
    for (int i = 0; i < 8; i++) {
        int rg = ti * 128 + r0 + i;
        float* p = out + (size_t)rg * OCOLS + colP + tj * 128 + c0;
        float4 v0 = make_float4(ev[i][0], ev[i][1], ev[i][2], ev[i][3]);
        float4 v1 = make_float4(ev[i][4], ev[i][5], ev[i][6], ev[i][7]);
        *reinterpret_cast<float4*>(p)     = v0;
        *reinterpret_cast<float4*>(p + 4) = v1;
        float s = v0.x + v0.y + v0.z + v0.w + v1.x + v1.y + v1.z + v1.w;
        atomicAdd(&rs_s[r0 + i], s);
    }
    #pragma unroll
    for (int j = 0; j < 8; j++) {
        float s = ev[0][j] + ev[1][j] + ev[2][j] + ev[3][j] +
                  ev[4][j] + ev[5][j] + ev[6][j] + ev[7][j];
        atomicAdd(&cs_s[c0 + j], s);
    }
    if (doT) {
        #pragma unroll
        for (int j = 0; j < 8; j++) {
            int cg = tj * 128 + c0 + j;
            float* p = out + (size_t)cg * OCOLS + colT + ti * 128 + r0;
            *reinterpret_cast<float4*>(p) =
                make_float4(ev[0][j], ev[1][j], ev[2][j], ev[3][j]);
            *reinterpret_cast<float4*>(p + 4) =
                make_float4(ev[4][j], ev[5][j], ev[6][j], ev[7][j]);
        }
    }

    __syncthreads();
    if (tid < 128) {
        float rv = rs_s[tid], cv = cs_s[tid];
        int rgi = ti * 128 + tid, cgi = tj * 128 + tid;
        if (jobType == 0) {
            atomicAdd(&g_sums[rgi], rv);            // ab rows -> part1 sums
            atomicAdd(&g_sums[NROWS + cgi], cv);    // ba rows -> part2 sums
        } else if (jobType == 1) {
            atomicAdd(&g_sums[rgi], rv);
            if (ti != tj) atomicAdd(&g_sums[cgi], cv);
        } else {
            atomicAdd(&g_sums[NROWS + rgi], rv);
            if (ti != tj) atomicAdd(&g_sums[NROWS + cgi], cv);
        }
    }
}

// ---------------- scale pass: out *= 1/rowsum ----------------
__global__ void scale_kernel(float4* __restrict__ out) {
    int idx = blockIdx.x * 256 + threadIdx.x;   // float4 index, 16M total
    int row = idx >> 12;                        // 4096 f4 per row
    int c4  = idx & 4095;
    float s = (c4 < 2048) ? g_sums[row] : g_sums[NROWS + row];
    float inv = __frcp_rn(s);
    float4 v = out[idx];
    v.x *= inv; v.y *= inv; v.z *= inv; v.w *= inv;
    out[idx] = v;
}

extern "C" void kernel_launch(void* const* d_in, const int* in_sizes, int n_in,
                              void* d_out, int out_size) {
    const float* z1 = (const float*)d_in[0];
    const float* z2 = (const float*)d_in[1];
    float* out = (float*)d_out;

    norm_kernel<<<2 * NROWS, 128>>>(z1, z2);
    gemm_exp_kernel<<<1024 + 528 + 528, 256>>>(out);
    scale_kernel<<<(NROWS * OCOLS / 4) / 256, 256>>>(reinterpret_cast<float4*>(out));
}

// round 9
// speedup vs baseline: 1.2619x; 1.2619x over previous
#include <cuda_runtime.h>
#include <cuda_bf16.h>
#include <cstdint>

// B=4096, D=128. out[4096][16384] fp32.
// part1 (cols 0..8191)  = softmax([a@b.T , a@a.T - diag*INF])
// part2 (cols 8192..)   = softmax([b@a.T , b@b.T - diag*INF])
// Logits in [-10,10] -> no max subtraction; diag masked to exactly 0.
// GEMM: split-bf16 (hi+lo, 3 products) on mma.sync.m16n8k16 (HMMA),
// fp32 register accumulators. (tcgen05 unavailable: harness targets compute_103.)

#define NROWS 4096
#define DDIM  128
#define OCOLS 16384

__device__ float g_sums[2 * NROWS];
__device__ __align__(256) __nv_bfloat16 g_ah[NROWS * DDIM];
__device__ __align__(256) __nv_bfloat16 g_al[NROWS * DDIM];
__device__ __align__(256) __nv_bfloat16 g_bh[NROWS * DDIM];
__device__ __align__(256) __nv_bfloat16 g_bl[NROWS * DDIM];

// ---------------- normalize + bf16 hi/lo split + zero sums ----------------
__global__ void norm_kernel(const float* __restrict__ z1,
                            const float* __restrict__ z2) {
    int row = blockIdx.x;           // 0..8191
    int tid = threadIdx.x;          // 0..127
    const float* src; __nv_bfloat16 *dh, *dl; int r;
    if (row < NROWS) { src = z1; dh = g_ah; dl = g_al; r = row; }
    else             { src = z2; dh = g_bh; dl = g_bl; r = row - NROWS; }
    float v = src[r * DDIM + tid];
    float s = v * v;
    #pragma unroll
    for (int o = 16; o; o >>= 1) s += __shfl_xor_sync(0xffffffffu, s, o);
    __shared__ float ws[4];
    if ((tid & 31) == 0) ws[tid >> 5] = s;
    __syncthreads();
    float tot = ws[0] + ws[1] + ws[2] + ws[3];
    float vn = v * rsqrtf(fmaxf(tot, 1e-12f));
    __nv_bfloat16 h = __float2bfloat16(vn);
    float hr = __bfloat162float(h);
    __nv_bfloat16 l = __float2bfloat16(vn - hr);
    dh[r * DDIM + tid] = h;
    dl[r * DDIM + tid] = l;
    if (tid == 0) g_sums[row] = 0.0f;
}

// ---------------- mma helpers ----------------
__device__ __forceinline__ void ldsm4(uint32_t* r, uint32_t addr) {
    asm volatile("ldmatrix.sync.aligned.m8n8.x4.shared.b16 {%0,%1,%2,%3}, [%4];"
                 : "=r"(r[0]), "=r"(r[1]), "=r"(r[2]), "=r"(r[3]) : "r"(addr));
}
__device__ __forceinline__ void ldsm2(uint32_t* r, uint32_t addr) {
    asm volatile("ldmatrix.sync.aligned.m8n8.x2.shared.b16 {%0,%1}, [%2];"
                 : "=r"(r[0]), "=r"(r[1]) : "r"(addr));
}
__device__ __forceinline__ void mma16816(float* d, const uint32_t* a, const uint32_t* b) {
    asm volatile(
        "mma.sync.aligned.m16n8k16.row.col.f32.bf16.bf16.f32 "
        "{%0,%1,%2,%3}, {%4,%5,%6,%7}, {%8,%9}, {%0,%1,%2,%3};"
        : "+f"(d[0]), "+f"(d[1]), "+f"(d[2]), "+f"(d[3])
        : "r"(a[0]), "r"(a[1]), "r"(a[2]), "r"(a[3]), "r"(b[0]), "r"(b[1]));
}
// Swizzled smem offset for a [128 rows x 128 bf16] tile: row stride 256B,
// 16B chunk index xor'ed with (row&7) -> conflict-free ldmatrix + stores.
__device__ __forceinline__ uint32_t swz(int row, int chunk) {
    return (uint32_t)(row * 256 + ((chunk ^ (row & 7)) << 4));
}

// SMEM tiles (dynamic): Ah, Al, Bh, Bl each 32 KB; rs_s after.
#define SM_AH 0
#define SM_AL 32768
#define SM_BH 65536
#define SM_BL 98304
#define SM_RS 131072
#define SM_TOTAL (131072 + 512)

// ---------------- fused HMMA GEMM + exp + rowsum ----------------
// grid = 4096: quad(4) x ti(32) x tj(32). 256 threads (8 warps).
// Warp tile 64x32: wm = wid&1 (row half), wn = wid>>1 (col quarter).
__global__ void __launch_bounds__(256, 1)
gemm_exp_kernel(float* __restrict__ out) {
    extern __shared__ char smem[];
    uint32_t sb = (uint32_t)__cvta_generic_to_shared(smem);
    float* rs_s = (float*)(smem + SM_RS);
    int tid = threadIdx.x, wid = tid >> 5, lane = tid & 31;

    int bi = blockIdx.x;
    int quad = bi >> 10;               // 0:ab 1:aa 2:ba 3:bb
    int rem  = bi & 1023;
    int ti = rem >> 5, tj = rem & 31;

    const __nv_bfloat16* Lh = (quad >= 2) ? g_bh : g_ah;
    const __nv_bfloat16* Ll = (quad >= 2) ? g_bl : g_al;
    bool rightB = (quad == 0) || (quad == 3);
    const __nv_bfloat16* Rh = rightB ? g_bh : g_ah;
    const __nv_bfloat16* Rl = rightB ? g_bl : g_al;
    bool diag = (quad & 1) && (ti == tj);
    int sumbase = (quad >= 2) ? NROWS : 0;

    const __nv_bfloat16* Ah = Lh + ti * 128 * DDIM;
    const __nv_bfloat16* Al = Ll + ti * 128 * DDIM;
    const __nv_bfloat16* Bh = Rh + tj * 128 * DDIM;
    const __nv_bfloat16* Bl = Rl + tj * 128 * DDIM;

    if (tid < 128) rs_s[tid] = 0.0f;

    // Load 4 tiles of 128x128 bf16 (2048 float4 chunks each tile).
    #pragma unroll
    for (int it = 0; it < 8; it++) {
        int i = tid + it * 256;         // chunk id 0..2047
        int r = i >> 4, c = i & 15;
        uint32_t so = swz(r, c);
        const float4* pa = (const float4*)(Ah + r * DDIM + c * 8);
        const float4* pl = (const float4*)(Al + r * DDIM + c * 8);
        const float4* pb = (const float4*)(Bh + r * DDIM + c * 8);
        const float4* pm = (const float4*)(Bl + r * DDIM + c * 8);
        *(float4*)(smem + SM_AH + so) = *pa;
        *(float4*)(smem + SM_AL + so) = *pl;
        *(float4*)(smem + SM_BH + so) = *pb;
        *(float4*)(smem + SM_BL + so) = *pm;
    }
    __syncthreads();

    int wm = wid & 1;                  // 0..1 : rows wm*64 + mt*16
    int wn = wid >> 1;                 // 0..3 : cols wn*32 + nt*8
    int g8 = lane & 7;
    int sel = lane >> 3;               // 0..3

    float acc[16][4];
    #pragma unroll
    for (int i = 0; i < 16; i++)
        #pragma unroll
        for (int j = 0; j < 4; j++) acc[i][j] = 0.0f;

    // 3 split products: (Ah,Bh), (Ah,Bl), (Al,Bh)
    #pragma unroll
    for (int pass = 0; pass < 3; pass++) {
        uint32_t abase = sb + ((pass == 2) ? SM_AL : SM_AH);
        uint32_t bbase = sb + ((pass == 1) ? SM_BL : SM_BH);
        #pragma unroll
        for (int ks = 0; ks < 8; ks++) {
            int kc = ks * 2;           // 16B-chunk index of k0
            uint32_t af[4][4], bf[4][2];
            #pragma unroll
            for (int mt = 0; mt < 4; mt++) {
                int row = wm * 64 + mt * 16 + g8 + ((sel & 1) << 3);
                int ch  = kc + (sel >> 1);
                ldsm4(af[mt], abase + swz(row, ch));
            }
            #pragma unroll
            for (int nt = 0; nt < 4; nt++) {
                int row = wn * 32 + nt * 8 + g8;
                int ch  = kc + (sel & 1);
                ldsm2(bf[nt], bbase + swz(row, ch));
            }
            #pragma unroll
            for (int mt = 0; mt < 4; mt++)
                #pragma unroll
                for (int nt = 0; nt < 4; nt++)
                    mma16816(acc[mt * 4 + nt], af[mt], bf[nt]);
        }
    }

    // ---- epilogue: exp, diag mask, store, rowsums ----
    int qr = lane >> 2;                // 0..7
    int qc = (lane & 3) * 2;           // 0,2,4,6
    #pragma unroll
    for (int mt = 0; mt < 4; mt++) {
        #pragma unroll
        for (int h = 0; h < 2; h++) {
            int rloc = wm * 64 + mt * 16 + h * 8 + qr;       // 0..127
            int grow = ti * 128 + rloc;
            float* rowp = out + (size_t)grow * OCOLS + quad * 4096 + tj * 128;
            float rsum = 0.0f;
            #pragma unroll
            for (int nt = 0; nt < 4; nt++) {
                int cloc = wn * 32 + nt * 8 + qc;
                const float* a = acc[mt * 4 + nt];
                float v0 = __expf(a[h * 2 + 0] * 10.0f);
                float v1 = __expf(a[h * 2 + 1] * 10.0f);
                if (diag) {
                    if (cloc == rloc)     v0 = 0.0f;
                    if (cloc + 1 == rloc) v1 = 0.0f;
                }
                rsum += v0 + v1;
                *(float2*)(rowp + cloc) = make_float2(v0, v1);
            }
            rsum += __shfl_xor_sync(0xffffffffu, rsum, 1);
            rsum += __shfl_xor_sync(0xffffffffu, rsum, 2);
            if ((lane & 3) == 0) atomicAdd(&rs_s[rloc], rsum);
        }
    }
    __syncthreads();
    if (tid < 128)
        atomicAdd(&g_sums[sumbase + ti * 128 + tid], rs_s[tid]);
}

// ---------------- scale pass: out *= 1/rowsum ----------------
__global__ void scale_kernel(float4* __restrict__ out) {
    int idx = blockIdx.x * 256 + threadIdx.x;   // float4 index, 16M total
    int row = idx >> 12;                        // 4096 f4 per row
    int c4  = idx & 4095;
    float s = (c4 < 2048) ? g_sums[row] : g_sums[NROWS + row];
    float inv = __frcp_rn(s);
    float4 v = out[idx];
    v.x *= inv; v.y *= inv; v.z *= inv; v.w *= inv;
    out[idx] = v;
}

extern "C" void kernel_launch(void* const* d_in, const int* in_sizes, int n_in,
                              void* d_out, int out_size) {
    const float* z1 = (const float*)d_in[0];
    const float* z2 = (const float*)d_in[1];
    float* out = (float*)d_out;

    cudaFuncSetAttribute(gemm_exp_kernel,
                         cudaFuncAttributeMaxDynamicSharedMemorySize, SM_TOTAL);

    norm_kernel<<<2 * NROWS, 128>>>(z1, z2);
    gemm_exp_kernel<<<4096, 256, SM_TOTAL>>>(out);
    scale_kernel<<<(NROWS * OCOLS / 4) / 256, 256>>>(reinterpret_cast<float4*>(out));
}

// round 10
// speedup vs baseline: 1.5864x; 1.2572x over previous
#include <cuda_runtime.h>
#include <cuda_bf16.h>
#include <cstdint>

// B=4096, D=128. out[4096][16384] fp32.
// part1 (cols 0..8191)  = softmax([a@b.T , a@a.T - diag*INF])
// part2 (cols 8192..)   = softmax([b@a.T , b@b.T - diag*INF])
// Logits in [-10,10] -> no max subtraction; diag masked to exactly 0.
// GEMM: split-bf16 (hi+lo, 3 products) on mma.sync.m16n8k16 (HMMA).
// Symmetry: ba = ab^T, aa/bb symmetric -> 2080 tiles instead of 4096;
// each tile written primary + transposed (via conflict-free smem stage).

#define NROWS 4096
#define DDIM  128
#define OCOLS 16384

__device__ float g_sums[2 * NROWS];
__device__ __align__(256) __nv_bfloat16 g_ah[NROWS * DDIM];
__device__ __align__(256) __nv_bfloat16 g_al[NROWS * DDIM];
__device__ __align__(256) __nv_bfloat16 g_bh[NROWS * DDIM];
__device__ __align__(256) __nv_bfloat16 g_bl[NROWS * DDIM];

// ---------------- normalize + bf16 hi/lo split + zero sums ----------------
__global__ void norm_kernel(const float* __restrict__ z1,
                            const float* __restrict__ z2) {
    int row = blockIdx.x;           // 0..8191
    int tid = threadIdx.x;          // 0..127
    const float* src; __nv_bfloat16 *dh, *dl; int r;
    if (row < NROWS) { src = z1; dh = g_ah; dl = g_al; r = row; }
    else             { src = z2; dh = g_bh; dl = g_bl; r = row - NROWS; }
    float v = src[r * DDIM + tid];
    float s = v * v;
    #pragma unroll
    for (int o = 16; o; o >>= 1) s += __shfl_xor_sync(0xffffffffu, s, o);
    __shared__ float ws[4];
    if ((tid & 31) == 0) ws[tid >> 5] = s;
    __syncthreads();
    float tot = ws[0] + ws[1] + ws[2] + ws[3];
    float vn = v * rsqrtf(fmaxf(tot, 1e-12f));
    __nv_bfloat16 h = __float2bfloat16(vn);
    float hr = __bfloat162float(h);
    __nv_bfloat16 l = __float2bfloat16(vn - hr);
    dh[r * DDIM + tid] = h;
    dl[r * DDIM + tid] = l;
    if (tid == 0) g_sums[row] = 0.0f;
}

// ---------------- mma helpers ----------------
__device__ __forceinline__ void ldsm4(uint32_t* r, uint32_t addr) {
    asm volatile("ldmatrix.sync.aligned.m8n8.x4.shared.b16 {%0,%1,%2,%3}, [%4];"
                 : "=r"(r[0]), "=r"(r[1]), "=r"(r[2]), "=r"(r[3]) : "r"(addr));
}
__device__ __forceinline__ void ldsm2(uint32_t* r, uint32_t addr) {
    asm volatile("ldmatrix.sync.aligned.m8n8.x2.shared.b16 {%0,%1}, [%2];"
                 : "=r"(r[0]), "=r"(r[1]) : "r"(addr));
}
__device__ __forceinline__ void mma16816(float* d, const uint32_t* a, const uint32_t* b) {
    asm volatile(
        "mma.sync.aligned.m16n8k16.row.col.f32.bf16.bf16.f32 "
        "{%0,%1,%2,%3}, {%4,%5,%6,%7}, {%8,%9}, {%0,%1,%2,%3};"
        : "+f"(d[0]), "+f"(d[1]), "+f"(d[2]), "+f"(d[3])
        : "r"(a[0]), "r"(a[1]), "r"(a[2]), "r"(a[3]), "r"(b[0]), "r"(b[1]));
}
// Swizzled smem offset for a [128 rows x 128 bf16] tile: row stride 256B,
// 16B chunk index xor'ed with (row&7) -> conflict-free ldmatrix + stores.
__device__ __forceinline__ uint32_t swz(int row, int chunk) {
    return (uint32_t)(row * 256 + ((chunk ^ (row & 7)) << 4));
}

// SMEM: operand tiles Ah/Al/Bh/Bl (32 KB each). After MMA the same region is
// reused as the transpose stage: 128 cols x 132-float stride = 67584 B.
#define SM_AH 0
#define SM_AL 32768
#define SM_BH 65536
#define SM_BL 98304
#define SM_RS 131072
#define SM_CS 131584
#define SM_TOTAL 132096
#define TSTRIDE 132

// ---------------- fused HMMA GEMM + exp + rowsums + dual write ----------------
// grid = 2080: 1024 AB + 528 AA(ti<=tj) + 528 BB(ti<=tj). 256 threads (8 warps).
__global__ void __launch_bounds__(256, 1)
gemm_exp_kernel(float* __restrict__ out) {
    extern __shared__ char smem[];
    uint32_t sb = (uint32_t)__cvta_generic_to_shared(smem);
    float* rs_s = (float*)(smem + SM_RS);
    float* cs_s = (float*)(smem + SM_CS);
    int tid = threadIdx.x, wid = tid >> 5, lane = tid & 31;

    // ---- job decode ----
    int bi = blockIdx.x;
    int job, ti, tj;                  // job: 0=ab 1=aa 2=bb
    if (bi < 1024) {
        job = 0; ti = bi >> 5; tj = bi & 31;
    } else {
        int t = bi - 1024;
        job = (t < 528) ? 1 : 2;
        int tt = (t < 528) ? t : t - 528;
        int i = 0;
        while (tt >= 32 - i) { tt -= 32 - i; i++; }
        ti = i; tj = i + tt;
    }
    const __nv_bfloat16* Lh = (job == 2) ? g_bh : g_ah;
    const __nv_bfloat16* Ll = (job == 2) ? g_bl : g_al;
    const __nv_bfloat16* Rh = (job == 1) ? g_ah : g_bh;
    const __nv_bfloat16* Rl = (job == 1) ? g_al : g_bl;
    bool diag = (job != 0) && (ti == tj);
    bool doT  = (job == 0) || (ti != tj);
    int quadP = (job == 0) ? 0 : (job == 1 ? 4096 : 12288);
    int quadT = (job == 0) ? 8192 : quadP;
    int colP = quadP + tj * 128;
    int colT = quadT + ti * 128;
    int sumP = (job == 2) ? NROWS : 0;
    int sumT = (job == 1) ? 0 : NROWS;

    const __nv_bfloat16* Ah = Lh + ti * 128 * DDIM;
    const __nv_bfloat16* Al = Ll + ti * 128 * DDIM;
    const __nv_bfloat16* Bh = Rh + tj * 128 * DDIM;
    const __nv_bfloat16* Bl = Rl + tj * 128 * DDIM;

    if (tid < 128) { rs_s[tid] = 0.0f; cs_s[tid] = 0.0f; }

    // ---- load 4 tiles of 128x128 bf16 ----
    #pragma unroll
    for (int it = 0; it < 8; it++) {
        int i = tid + it * 256;         // chunk id 0..2047
        int r = i >> 4, c = i & 15;
        uint32_t so = swz(r, c);
        *(float4*)(smem + SM_AH + so) = *(const float4*)(Ah + r * DDIM + c * 8);
        *(float4*)(smem + SM_AL + so) = *(const float4*)(Al + r * DDIM + c * 8);
        *(float4*)(smem + SM_BH + so) = *(const float4*)(Bh + r * DDIM + c * 8);
        *(float4*)(smem + SM_BL + so) = *(const float4*)(Bl + r * DDIM + c * 8);
    }
    __syncthreads();

    int wm = wid & 1;                  // row half
    int wn = wid >> 1;                 // col quarter
    int g8 = lane & 7;
    int sel = lane >> 3;

    float acc[16][4];
    #pragma unroll
    for (int i = 0; i < 16; i++)
        #pragma unroll
        for (int j = 0; j < 4; j++) acc[i][j] = 0.0f;

    // 3 split products: (Ah,Bh), (Ah,Bl), (Al,Bh)
    #pragma unroll
    for (int pass = 0; pass < 3; pass++) {
        uint32_t abase = sb + ((pass == 2) ? SM_AL : SM_AH);
        uint32_t bbase = sb + ((pass == 1) ? SM_BL : SM_BH);
        #pragma unroll
        for (int ks = 0; ks < 8; ks++) {
            int kc = ks * 2;
            uint32_t af[4][4], bf[4][2];
            #pragma unroll
            for (int mt = 0; mt < 4; mt++) {
                int row = wm * 64 + mt * 16 + g8 + ((sel & 1) << 3);
                ldsm4(af[mt], abase + swz(row, kc + (sel >> 1)));
            }
            #pragma unroll
            for (int nt = 0; nt < 4; nt++) {
                int row = wn * 32 + nt * 8 + g8;
                ldsm2(bf[nt], bbase + swz(row, kc + (sel & 1)));
            }
            #pragma unroll
            for (int mt = 0; mt < 4; mt++)
                #pragma unroll
                for (int nt = 0; nt < 4; nt++)
                    mma16816(acc[mt * 4 + nt], af[mt], bf[nt]);
        }
    }
    __syncthreads();     // all warps done reading operand smem -> stage reuse ok

    // ---- exp in place + diag mask ----
    int qr = lane >> 2;                // 0..7
    int qc = (lane & 3) * 2;           // 0,2,4,6
    #pragma unroll
    for (int mt = 0; mt < 4; mt++)
        #pragma unroll
        for (int nt = 0; nt < 4; nt++) {
            float* a = acc[mt * 4 + nt];
            #pragma unroll
            for (int j = 0; j < 4; j++) a[j] = __expf(a[j] * 10.0f);
            if (diag) {
                int cl = wn * 32 + nt * 8 + qc;
                #pragma unroll
                for (int h = 0; h < 2; h++) {
                    int rl = wm * 64 + mt * 16 + h * 8 + qr;
                    if (cl == rl)     a[h * 2 + 0] = 0.0f;
                    if (cl + 1 == rl) a[h * 2 + 1] = 0.0f;
                }
            }
        }

    // ---- primary stores + row sums ----
    #pragma unroll
    for (int mt = 0; mt < 4; mt++) {
        #pragma unroll
        for (int h = 0; h < 2; h++) {
            int rloc = wm * 64 + mt * 16 + h * 8 + qr;
            int grow = ti * 128 + rloc;
            float* rowp = out + (size_t)grow * OCOLS + colP;
            float rsum = 0.0f;
            #pragma unroll
            for (int nt = 0; nt < 4; nt++) {
                int cloc = wn * 32 + nt * 8 + qc;
                const float* a = acc[mt * 4 + nt];
                float v0 = a[h * 2 + 0], v1 = a[h * 2 + 1];
                rsum += v0 + v1;
                *(float2*)(rowp + cloc) = make_float2(v0, v1);
            }
            rsum += __shfl_xor_sync(0xffffffffu, rsum, 1);
            rsum += __shfl_xor_sync(0xffffffffu, rsum, 2);
            if ((lane & 3) == 0) atomicAdd(&rs_s[rloc], rsum);
        }
    }

    // ---- column sums (for transposed rows) ----
    #pragma unroll
    for (int nt = 0; nt < 4; nt++) {
        float c0s = 0.0f, c1s = 0.0f;
        #pragma unroll
        for (int mt = 0; mt < 4; mt++) {
            const float* a = acc[mt * 4 + nt];
            c0s += a[0] + a[2];
            c1s += a[1] + a[3];
        }
        #pragma unroll
        for (int o = 4; o <= 16; o <<= 1) {
            c0s += __shfl_xor_sync(0xffffffffu, c0s, o);
            c1s += __shfl_xor_sync(0xffffffffu, c1s, o);
        }
        if (lane < 4) {
            int cloc = wn * 32 + nt * 8 + qc;
            atomicAdd(&cs_s[cloc], c0s);
            atomicAdd(&cs_s[cloc + 1], c1s);
        }
    }

    // ---- stage transposed tile: stg[c * 132 + r] (conflict-free scatter) ----
    if (doT) {
        float* stg = (float*)smem;
        #pragma unroll
        for (int mt = 0; mt < 4; mt++)
            #pragma unroll
            for (int nt = 0; nt < 4; nt++) {
                const float* a = acc[mt * 4 + nt];
                int cloc = wn * 32 + nt * 8 + qc;
                #pragma unroll
                for (int h = 0; h < 2; h++) {
                    int rloc = wm * 64 + mt * 16 + h * 8 + qr;
                    stg[cloc * TSTRIDE + rloc]       = a[h * 2 + 0];
                    stg[(cloc + 1) * TSTRIDE + rloc] = a[h * 2 + 1];
                }
            }
    }
    __syncthreads();

    // ---- transposed coalesced writes ----
    if (doT) {
        const float* stg = (const float*)smem;
        #pragma unroll
        for (int rr = 0; rr < 16; rr++) {
            int c = wid * 16 + rr;
            float4 v = *(const float4*)(stg + c * TSTRIDE + lane * 4);
            int trow = tj * 128 + c;
            *(float4*)(out + (size_t)trow * OCOLS + colT + lane * 4) = v;
        }
    }

    // ---- global sum accumulation ----
    if (tid < 128) {
        atomicAdd(&g_sums[sumP + ti * 128 + tid], rs_s[tid]);
        if (doT) atomicAdd(&g_sums[sumT + tj * 128 + tid], cs_s[tid]);
    }
}

// ---------------- scale pass: out *= 1/rowsum ----------------
__global__ void scale_kernel(float4* __restrict__ out) {
    int idx = blockIdx.x * 256 + threadIdx.x;   // float4 index, 16M total
    int row = idx >> 12;                        // 4096 f4 per row
    int c4  = idx & 4095;
    float s = (c4 < 2048) ? g_sums[row] : g_sums[NROWS + row];
    float inv = __frcp_rn(s);
    float4 v = out[idx];
    v.x *= inv; v.y *= inv; v.z *= inv; v.w *= inv;
    out[idx] = v;
}

extern "C" void kernel_launch(void* const* d_in, const int* in_sizes, int n_in,
                              void* d_out, int out_size) {
    const float* z1 = (const float*)d_in[0];
    const float* z2 = (const float*)d_in[1];
    float* out = (float*)d_out;

    cudaFuncSetAttribute(gemm_exp_kernel,
                         cudaFuncAttributeMaxDynamicSharedMemorySize, SM_TOTAL);

    norm_kernel<<<2 * NROWS, 128>>>(z1, z2);
    gemm_exp_kernel<<<2080, 256, SM_TOTAL>>>(out);
    scale_kernel<<<(NROWS * OCOLS / 4) / 256, 256>>>(reinterpret_cast<float4*>(out));
}

// round 11
// speedup vs baseline: 1.7983x; 1.1336x over previous
#include <cuda_runtime.h>
#include <cuda_bf16.h>
#include <cuda_fp16.h>
#include <cstdint>

// B=4096, D=128. out[4096][16384] fp32.
// part1 (cols 0..8191)  = softmax([a@b.T , a@a.T - diag*INF])
// part2 (cols 8192..)   = softmax([b@a.T , b@b.T - diag*INF])
// Logits ~[-4.5,4.5] -> no max subtraction; diag masked to exactly 0.
// GEMM: split-bf16 (hi+lo, 3 products) on mma.sync.m16n8k16 (HMMA).
// Symmetry: ba = ab^T, aa/bb symmetric -> 2080 tiles.
// Unnormalized exp staged in fp16 (exp in [0.011, 90], normal range);
// scale pass reads fp16, writes scaled fp32 -> 512 MB total DRAM vs 768.

#define NROWS 4096
#define DDIM  128
#define OCOLS 16384

__device__ float g_sums[2 * NROWS];
__device__ __align__(256) __nv_bfloat16 g_ah[NROWS * DDIM];
__device__ __align__(256) __nv_bfloat16 g_al[NROWS * DDIM];
__device__ __align__(256) __nv_bfloat16 g_bh[NROWS * DDIM];
__device__ __align__(256) __nv_bfloat16 g_bl[NROWS * DDIM];
__device__ __align__(256) __half g_stage[(size_t)NROWS * OCOLS];   // 128 MB fp16 exp stage

// ---------------- normalize + bf16 hi/lo split + zero sums ----------------
__global__ void norm_kernel(const float* __restrict__ z1,
                            const float* __restrict__ z2) {
    int row = blockIdx.x;           // 0..8191
    int tid = threadIdx.x;          // 0..127
    const float* src; __nv_bfloat16 *dh, *dl; int r;
    if (row < NROWS) { src = z1; dh = g_ah; dl = g_al; r = row; }
    else             { src = z2; dh = g_bh; dl = g_bl; r = row - NROWS; }
    float v = src[r * DDIM + tid];
    float s = v * v;
    #pragma unroll
    for (int o = 16; o; o >>= 1) s += __shfl_xor_sync(0xffffffffu, s, o);
    __shared__ float ws[4];
    if ((tid & 31) == 0) ws[tid >> 5] = s;
    __syncthreads();
    float tot = ws[0] + ws[1] + ws[2] + ws[3];
    float vn = v * rsqrtf(fmaxf(tot, 1e-12f));
    __nv_bfloat16 h = __float2bfloat16(vn);
    float hr = __bfloat162float(h);
    __nv_bfloat16 l = __float2bfloat16(vn - hr);
    dh[r * DDIM + tid] = h;
    dl[r * DDIM + tid] = l;
    if (tid == 0) g_sums[row] = 0.0f;
}

// ---------------- mma helpers ----------------
__device__ __forceinline__ void ldsm4(uint32_t* r, uint32_t addr) {
    asm volatile("ldmatrix.sync.aligned.m8n8.x4.shared.b16 {%0,%1,%2,%3}, [%4];"
                 : "=r"(r[0]), "=r"(r[1]), "=r"(r[2]), "=r"(r[3]) : "r"(addr));
}
__device__ __forceinline__ void ldsm2(uint32_t* r, uint32_t addr) {
    asm volatile("ldmatrix.sync.aligned.m8n8.x2.shared.b16 {%0,%1}, [%2];"
                 : "=r"(r[0]), "=r"(r[1]) : "r"(addr));
}
__device__ __forceinline__ void mma16816(float* d, const uint32_t* a, const uint32_t* b) {
    asm volatile(
        "mma.sync.aligned.m16n8k16.row.col.f32.bf16.bf16.f32 "
        "{%0,%1,%2,%3}, {%4,%5,%6,%7}, {%8,%9}, {%0,%1,%2,%3};"
        : "+f"(d[0]), "+f"(d[1]), "+f"(d[2]), "+f"(d[3])
        : "r"(a[0]), "r"(a[1]), "r"(a[2]), "r"(a[3]), "r"(b[0]), "r"(b[1]));
}
// Swizzled smem offset for a [128 rows x 128 bf16] tile: row stride 256B,
// 16B chunk index xor'ed with (row&7) -> conflict-free ldmatrix + stores.
__device__ __forceinline__ uint32_t swz(int row, int chunk) {
    return (uint32_t)(row * 256 + ((chunk ^ (row & 7)) << 4));
}

// SMEM: operand tiles Ah/Al/Bh/Bl (32 KB each). After MMA, [0,33792) is
// reused as the fp16 transpose stage: 64 col-pair rows x 132 u32.
#define SM_AH 0
#define SM_AL 32768
#define SM_BH 65536
#define SM_BL 98304
#define SM_RS 131072
#define SM_CS 131584
#define SM_TOTAL 132096
#define TSTRIDE 132

// ---------------- fused HMMA GEMM + exp + rowsums + dual fp16 write ----------------
// grid = 2080: 1024 AB + 528 AA(ti<=tj) + 528 BB(ti<=tj). 256 threads (8 warps).
__global__ void __launch_bounds__(256, 1)
gemm_exp_kernel() {
    extern __shared__ char smem[];
    uint32_t sb = (uint32_t)__cvta_generic_to_shared(smem);
    float* rs_s = (float*)(smem + SM_RS);
    float* cs_s = (float*)(smem + SM_CS);
    int tid = threadIdx.x, wid = tid >> 5, lane = tid & 31;

    // ---- job decode ----
    int bi = blockIdx.x;
    int job, ti, tj;                  // job: 0=ab 1=aa 2=bb
    if (bi < 1024) {
        job = 0; ti = bi >> 5; tj = bi & 31;
    } else {
        int t = bi - 1024;
        job = (t < 528) ? 1 : 2;
        int tt = (t < 528) ? t : t - 528;
        int i = 0;
        while (tt >= 32 - i) { tt -= 32 - i; i++; }
        ti = i; tj = i + tt;
    }
    const __nv_bfloat16* Lh = (job == 2) ? g_bh : g_ah;
    const __nv_bfloat16* Ll = (job == 2) ? g_bl : g_al;
    const __nv_bfloat16* Rh = (job == 1) ? g_ah : g_bh;
    const __nv_bfloat16* Rl = (job == 1) ? g_al : g_bl;
    bool diag = (job != 0) && (ti == tj);
    bool doT  = (job == 0) || (ti != tj);
    int quadP = (job == 0) ? 0 : (job == 1 ? 4096 : 12288);
    int quadT = (job == 0) ? 8192 : quadP;
    int colP = quadP + tj * 128;
    int colT = quadT + ti * 128;
    int sumP = (job == 2) ? NROWS : 0;
    int sumT = (job == 1) ? 0 : NROWS;

    const __nv_bfloat16* Ah = Lh + ti * 128 * DDIM;
    const __nv_bfloat16* Al = Ll + ti * 128 * DDIM;
    const __nv_bfloat16* Bh = Rh + tj * 128 * DDIM;
    const __nv_bfloat16* Bl = Rl + tj * 128 * DDIM;

    if (tid < 128) { rs_s[tid] = 0.0f; cs_s[tid] = 0.0f; }

    // ---- load 4 tiles of 128x128 bf16 ----
    #pragma unroll
    for (int it = 0; it < 8; it++) {
        int i = tid + it * 256;         // chunk id 0..2047
        int r = i >> 4, c = i & 15;
        uint32_t so = swz(r, c);
        *(float4*)(smem + SM_AH + so) = *(const float4*)(Ah + r * DDIM + c * 8);
        *(float4*)(smem + SM_AL + so) = *(const float4*)(Al + r * DDIM + c * 8);
        *(float4*)(smem + SM_BH + so) = *(const float4*)(Bh + r * DDIM + c * 8);
        *(float4*)(smem + SM_BL + so) = *(const float4*)(Bl + r * DDIM + c * 8);
    }
    __syncthreads();

    int wm = wid & 1;                  // row half
    int wn = wid >> 1;                 // col quarter
    int g8 = lane & 7;
    int sel = lane >> 3;

    float acc[16][4];
    #pragma unroll
    for (int i = 0; i < 16; i++)
        #pragma unroll
        for (int j = 0; j < 4; j++) acc[i][j] = 0.0f;

    // 3 split products: (Ah,Bh), (Ah,Bl), (Al,Bh)
    #pragma unroll
    for (int pass = 0; pass < 3; pass++) {
        uint32_t abase = sb + ((pass == 2) ? SM_AL : SM_AH);
        uint32_t bbase = sb + ((pass == 1) ? SM_BL : SM_BH);
        #pragma unroll
        for (int ks = 0; ks < 8; ks++) {
            int kc = ks * 2;
            uint32_t af[4][4], bf[4][2];
            #pragma unroll
            for (int mt = 0; mt < 4; mt++) {
                int row = wm * 64 + mt * 16 + g8 + ((sel & 1) << 3);
                ldsm4(af[mt], abase + swz(row, kc + (sel >> 1)));
            }
            #pragma unroll
            for (int nt = 0; nt < 4; nt++) {
                int row = wn * 32 + nt * 8 + g8;
                ldsm2(bf[nt], bbase + swz(row, kc + (sel & 1)));
            }
            #pragma unroll
            for (int mt = 0; mt < 4; mt++)
                #pragma unroll
                for (int nt = 0; nt < 4; nt++)
                    mma16816(acc[mt * 4 + nt], af[mt], bf[nt]);
        }
    }
    __syncthreads();     // all warps done reading operand smem -> stage reuse ok

    // ---- exp in place + diag mask ----
    int qr = lane >> 2;                // 0..7
    int qc = (lane & 3) * 2;           // 0,2,4,6
    #pragma unroll
    for (int mt = 0; mt < 4; mt++)
        #pragma unroll
        for (int nt = 0; nt < 4; nt++) {
            float* a = acc[mt * 4 + nt];
            #pragma unroll
            for (int j = 0; j < 4; j++) a[j] = __expf(a[j] * 10.0f);
            if (diag) {
                int cl = wn * 32 + nt * 8 + qc;
                #pragma unroll
                for (int h = 0; h < 2; h++) {
                    int rl = wm * 64 + mt * 16 + h * 8 + qr;
                    if (cl == rl)     a[h * 2 + 0] = 0.0f;
                    if (cl + 1 == rl) a[h * 2 + 1] = 0.0f;
                }
            }
        }

    // ---- primary fp16 stores + row sums ----
    #pragma unroll
    for (int mt = 0; mt < 4; mt++) {
        #pragma unroll
        for (int h = 0; h < 2; h++) {
            int rloc = wm * 64 + mt * 16 + h * 8 + qr;
            int grow = ti * 128 + rloc;
            __half* rowp = g_stage + (size_t)grow * OCOLS + colP;
            float rsum = 0.0f;
            #pragma unroll
            for (int nt = 0; nt < 4; nt++) {
                int cloc = wn * 32 + nt * 8 + qc;
                const float* a = acc[mt * 4 + nt];
                float v0 = a[h * 2 + 0], v1 = a[h * 2 + 1];
                rsum += v0 + v1;
                *(__half2*)(rowp + cloc) = __floats2half2_rn(v0, v1);
            }
            rsum += __shfl_xor_sync(0xffffffffu, rsum, 1);
            rsum += __shfl_xor_sync(0xffffffffu, rsum, 2);
            if ((lane & 3) == 0) atomicAdd(&rs_s[rloc], rsum);
        }
    }

    // ---- column sums (for transposed rows) ----
    #pragma unroll
    for (int nt = 0; nt < 4; nt++) {
        float c0s = 0.0f, c1s = 0.0f;
        #pragma unroll
        for (int mt = 0; mt < 4; mt++) {
            const float* a = acc[mt * 4 + nt];
            c0s += a[0] + a[2];
            c1s += a[1] + a[3];
        }
        #pragma unroll
        for (int o = 4; o <= 16; o <<= 1) {
            c0s += __shfl_xor_sync(0xffffffffu, c0s, o);
            c1s += __shfl_xor_sync(0xffffffffu, c1s, o);
        }
        if (lane < 4) {
            int cloc = wn * 32 + nt * 8 + qc;
            atomicAdd(&cs_s[cloc], c0s);
            atomicAdd(&cs_s[cloc + 1], c1s);
        }
    }

    // ---- stage transposed tile as packed half2: stg[(c>>1)*132 + r] ----
    if (doT) {
        uint32_t* stg = (uint32_t*)smem;
        #pragma unroll
        for (int mt = 0; mt < 4; mt++)
            #pragma unroll
            for (int nt = 0; nt < 4; nt++) {
                const float* a = acc[mt * 4 + nt];
                int cp = (wn * 32 + nt * 8 + qc) >> 1;   // col-pair index
                #pragma unroll
                for (int h = 0; h < 2; h++) {
                    int rloc = wm * 64 + mt * 16 + h * 8 + qr;
                    __half2 hv = __floats2half2_rn(a[h * 2 + 0], a[h * 2 + 1]);
                    stg[cp * TSTRIDE + rloc] = *reinterpret_cast<uint32_t*>(&hv);
                }
            }
    }
    __syncthreads();

    // ---- transposed coalesced fp16 writes (split low/high halves) ----
    if (doT) {
        const uint32_t* stg = (const uint32_t*)smem;
        #pragma unroll
        for (int rr = 0; rr < 8; rr++) {
            int cp = wid * 8 + rr;                        // 0..63
            uint4 q = *(const uint4*)(stg + cp * TSTRIDE + lane * 4);
            uint32_t l0 = __byte_perm(q.x, q.y, 0x5410);
            uint32_t l1 = __byte_perm(q.z, q.w, 0x5410);
            uint32_t h0 = __byte_perm(q.x, q.y, 0x7632);
            uint32_t h1 = __byte_perm(q.z, q.w, 0x7632);
            size_t base = (size_t)(tj * 128 + 2 * cp) * OCOLS + colT + lane * 4;
            *(uint2*)(g_stage + base)         = make_uint2(l0, l1);
            *(uint2*)(g_stage + base + OCOLS) = make_uint2(h0, h1);
        }
    }

    // ---- global sum accumulation ----
    if (tid < 128) {
        atomicAdd(&g_sums[sumP + ti * 128 + tid], rs_s[tid]);
        if (doT) atomicAdd(&g_sums[sumT + tj * 128 + tid], cs_s[tid]);
    }
}

// ---------------- scale pass: out = fp16_stage * (1/rowsum) ----------------
__global__ void scale_kernel(float4* __restrict__ out) {
    int idx = blockIdx.x * 256 + threadIdx.x;   // float4 index, 16M total
    int row = idx >> 12;                        // 4096 f4 per row
    int c4  = idx & 4095;
    float s = (c4 < 2048) ? g_sums[row] : g_sums[NROWS + row];
    float inv = __frcp_rn(s);
    uint2 st = *(const uint2*)(g_stage + (size_t)idx * 4);
    __half2 p0 = *reinterpret_cast<__half2*>(&st.x);
    __half2 p1 = *reinterpret_cast<__half2*>(&st.y);
    float2 f0 = __half22float2(p0);
    float2 f1 = __half22float2(p1);
    out[idx] = make_float4(f0.x * inv, f0.y * inv, f1.x * inv, f1.y * inv);
}

extern "C" void kernel_launch(void* const* d_in, const int* in_sizes, int n_in,
                              void* d_out, int out_size) {
    const float* z1 = (const float*)d_in[0];
    const float* z2 = (const float*)d_in[1];
    float* out = (float*)d_out;

    cudaFuncSetAttribute(gemm_exp_kernel,
                         cudaFuncAttributeMaxDynamicSharedMemorySize, SM_TOTAL);

    norm_kernel<<<2 * NROWS, 128>>>(z1, z2);
    gemm_exp_kernel<<<2080, 256, SM_TOTAL>>>();
    scale_kernel<<<(NROWS * OCOLS / 4) / 256, 256>>>(reinterpret_cast<float4*>(out));
}

// round 12
// speedup vs baseline: 2.1880x; 1.2167x over previous
#include <cuda_runtime.h>
#include <cuda_bf16.h>
#include <cuda_fp16.h>
#include <cstdint>

// B=4096, D=128. out[4096][16384] fp32.
// part1 (cols 0..8191)  = softmax([a@b.T , a@a.T - diag*INF])
// part2 (cols 8192..)   = softmax([b@a.T , b@b.T - diag*INF])
// Logits ~[-4.5,4.5] -> no max subtraction; diag masked to exactly 0.
// GEMM: split-bf16 (hi+lo, 3 products) on mma.sync.m16n8k16 (HMMA).
// Symmetry: 2080 tiles (ab + upper-tri aa/bb), dual primary/transposed writes.
// fp16 stage for unnormalized exp; scale pass emits fp32.
// This round: 97 KB smem (3 operand buffers, cp.async groups) -> 2 CTAs/SM
// so load/epilogue of one CTA overlaps the sibling's MMA.

#define NROWS 4096
#define DDIM  128
#define OCOLS 16384

__device__ float g_sums[2 * NROWS];
__device__ __align__(256) __nv_bfloat16 g_ah[NROWS * DDIM];
__device__ __align__(256) __nv_bfloat16 g_al[NROWS * DDIM];
__device__ __align__(256) __nv_bfloat16 g_bh[NROWS * DDIM];
__device__ __align__(256) __nv_bfloat16 g_bl[NROWS * DDIM];
__device__ __align__(256) __half g_stage[(size_t)NROWS * OCOLS];   // 128 MB fp16 exp stage

// ---------------- normalize + bf16 hi/lo split + zero sums ----------------
__global__ void norm_kernel(const float* __restrict__ z1,
                            const float* __restrict__ z2) {
    int row = blockIdx.x;           // 0..8191
    int tid = threadIdx.x;          // 0..127
    const float* src; __nv_bfloat16 *dh, *dl; int r;
    if (row < NROWS) { src = z1; dh = g_ah; dl = g_al; r = row; }
    else             { src = z2; dh = g_bh; dl = g_bl; r = row - NROWS; }
    float v = src[r * DDIM + tid];
    float s = v * v;
    #pragma unroll
    for (int o = 16; o; o >>= 1) s += __shfl_xor_sync(0xffffffffu, s, o);
    __shared__ float ws[4];
    if ((tid & 31) == 0) ws[tid >> 5] = s;
    __syncthreads();
    float tot = ws[0] + ws[1] + ws[2] + ws[3];
    float vn = v * rsqrtf(fmaxf(tot, 1e-12f));
    __nv_bfloat16 h = __float2bfloat16(vn);
    float hr = __bfloat162float(h);
    __nv_bfloat16 l = __float2bfloat16(vn - hr);
    dh[r * DDIM + tid] = h;
    dl[r * DDIM + tid] = l;
    if (tid == 0) g_sums[row] = 0.0f;
}

// ---------------- mma / cp.async helpers ----------------
__device__ __forceinline__ void ldsm4(uint32_t* r, uint32_t addr) {
    asm volatile("ldmatrix.sync.aligned.m8n8.x4.shared.b16 {%0,%1,%2,%3}, [%4];"
                 : "=r"(r[0]), "=r"(r[1]), "=r"(r[2]), "=r"(r[3]) : "r"(addr));
}
__device__ __forceinline__ void ldsm2(uint32_t* r, uint32_t addr) {
    asm volatile("ldmatrix.sync.aligned.m8n8.x2.shared.b16 {%0,%1}, [%2];"
                 : "=r"(r[0]), "=r"(r[1]) : "r"(addr));
}
__device__ __forceinline__ void mma16816(float* d, const uint32_t* a, const uint32_t* b) {
    asm volatile(
        "mma.sync.aligned.m16n8k16.row.col.f32.bf16.bf16.f32 "
        "{%0,%1,%2,%3}, {%4,%5,%6,%7}, {%8,%9}, {%0,%1,%2,%3};"
        : "+f"(d[0]), "+f"(d[1]), "+f"(d[2]), "+f"(d[3])
        : "r"(a[0]), "r"(a[1]), "r"(a[2]), "r"(a[3]), "r"(b[0]), "r"(b[1]));
}
__device__ __forceinline__ void cpa16(uint32_t dst, const void* src) {
    asm volatile("cp.async.cg.shared.global [%0], [%1], 16;" :: "r"(dst), "l"(src));
}
#define CP_COMMIT() asm volatile("cp.async.commit_group;")
#define CP_WAIT(n)  asm volatile("cp.async.wait_group %0;" :: "n"(n))

// Swizzled smem offset for a [128 rows x 128 bf16] tile: row stride 256B,
// 16B chunk index xor'ed with (row&7) -> conflict-free ldmatrix + stores.
__device__ __forceinline__ uint32_t swz(int row, int chunk) {
    return (uint32_t)(row * 256 + ((chunk ^ (row & 7)) << 4));
}

// SMEM: P=Ah (resident), Q=Bh, R=Al then Bl. 32 KB each.
// Transpose stage (34816 B) reuses [0, 34816) after all MMA passes.
#define SM_P 0
#define SM_Q 32768
#define SM_R 65536
#define SM_RS 98304
#define SM_CS 98816
#define SM_TOTAL 99328
#define TSTRIDE 136   // words; banks = 4*colpair + row -> conflict-free scatter

// ---------------- fused HMMA GEMM + exp + rowsums + dual fp16 write ----------------
// grid = 2080: 1024 AB + 528 AA(ti<=tj) + 528 BB(ti<=tj). 256 threads (8 warps).
__global__ void __launch_bounds__(256, 2)
gemm_exp_kernel() {
    extern __shared__ char smem[];
    uint32_t sb = (uint32_t)__cvta_generic_to_shared(smem);
    float* rs_s = (float*)(smem + SM_RS);
    float* cs_s = (float*)(smem + SM_CS);
    int tid = threadIdx.x, wid = tid >> 5, lane = tid & 31;

    // ---- job decode ----
    int bi = blockIdx.x;
    int job, ti, tj;                  // job: 0=ab 1=aa 2=bb
    if (bi < 1024) {
        job = 0; ti = bi >> 5; tj = bi & 31;
    } else {
        int t = bi - 1024;
        job = (t < 528) ? 1 : 2;
        int tt = (t < 528) ? t : t - 528;
        int i = 0;
        while (tt >= 32 - i) { tt -= 32 - i; i++; }
        ti = i; tj = i + tt;
    }
    const __nv_bfloat16* Lh = (job == 2) ? g_bh : g_ah;
    const __nv_bfloat16* Ll = (job == 2) ? g_bl : g_al;
    const __nv_bfloat16* Rh = (job == 1) ? g_ah : g_bh;
    const __nv_bfloat16* Rl = (job == 1) ? g_al : g_bl;
    bool diag = (job != 0) && (ti == tj);
    bool doT  = (job == 0) || (ti != tj);
    int quadP = (job == 0) ? 0 : (job == 1 ? 4096 : 12288);
    int quadT = (job == 0) ? 8192 : quadP;
    int colP = quadP + tj * 128;
    int colT = quadT + ti * 128;
    int sumP = (job == 2) ? NROWS : 0;
    int sumT = (job == 1) ? 0 : NROWS;

    const __nv_bfloat16* Ah = Lh + ti * 128 * DDIM;
    const __nv_bfloat16* Al = Ll + ti * 128 * DDIM;
    const __nv_bfloat16* Bh = Rh + tj * 128 * DDIM;
    const __nv_bfloat16* Bl = Rl + tj * 128 * DDIM;

    if (tid < 128) { rs_s[tid] = 0.0f; cs_s[tid] = 0.0f; }

    // ---- async loads: g0 = {Ah->P, Bh->Q}, g1 = {Al->R} ----
    #pragma unroll
    for (int it = 0; it < 8; it++) {
        int i = tid + it * 256;         // chunk id 0..2047
        int r = i >> 4, c = i & 15;
        uint32_t so = swz(r, c);
        cpa16(sb + SM_P + so, Ah + r * DDIM + c * 8);
        cpa16(sb + SM_Q + so, Bh + r * DDIM + c * 8);
    }
    CP_COMMIT();
    #pragma unroll
    for (int it = 0; it < 8; it++) {
        int i = tid + it * 256;
        int r = i >> 4, c = i & 15;
        cpa16(sb + SM_R + swz(r, c), Al + r * DDIM + c * 8);
    }
    CP_COMMIT();

    int wm = wid & 1;                  // row half
    int wn = wid >> 1;                 // col quarter
    int g8 = lane & 7;
    int sel = lane >> 3;

    float acc[16][4];
    #pragma unroll
    for (int i = 0; i < 16; i++)
        #pragma unroll
        for (int j = 0; j < 4; j++) acc[i][j] = 0.0f;

    // One MMA pass over K=128 from (abase, bbase)
    auto mma_pass = [&](uint32_t abase, uint32_t bbase) {
        #pragma unroll
        for (int ks = 0; ks < 8; ks++) {
            int kc = ks * 2;
            uint32_t af[4][4], bf[4][2];
            #pragma unroll
            for (int mt = 0; mt < 4; mt++) {
                int row = wm * 64 + mt * 16 + g8 + ((sel & 1) << 3);
                ldsm4(af[mt], abase + swz(row, kc + (sel >> 1)));
            }
            #pragma unroll
            for (int nt = 0; nt < 4; nt++) {
                int row = wn * 32 + nt * 8 + g8;
                ldsm2(bf[nt], bbase + swz(row, kc + (sel & 1)));
            }
            #pragma unroll
            for (int mt = 0; mt < 4; mt++)
                #pragma unroll
                for (int nt = 0; nt < 4; nt++)
                    mma16816(acc[mt * 4 + nt], af[mt], bf[nt]);
        }
    };

    CP_WAIT(1);                // Ah, Bh arrived (Al may still be in flight)
    __syncthreads();
    mma_pass(sb + SM_P, sb + SM_Q);          // hh
    CP_WAIT(0);                // Al arrived
    __syncthreads();
    mma_pass(sb + SM_R, sb + SM_Q);          // lh  (Al * Bh)
    __syncthreads();           // all warps done reading R
    #pragma unroll
    for (int it = 0; it < 8; it++) {
        int i = tid + it * 256;
        int r = i >> 4, c = i & 15;
        cpa16(sb + SM_R + swz(r, c), Bl + r * DDIM + c * 8);
    }
    CP_COMMIT();
    CP_WAIT(0);
    __syncthreads();
    mma_pass(sb + SM_P, sb + SM_R);          // hl  (Ah * Bl)
    __syncthreads();           // operand smem free -> stage reuse ok

    // ---- exp in place + diag mask ----
    int qr = lane >> 2;                // 0..7
    int qc = (lane & 3) * 2;           // 0,2,4,6
    #pragma unroll
    for (int mt = 0; mt < 4; mt++)
        #pragma unroll
        for (int nt = 0; nt < 4; nt++) {
            float* a = acc[mt * 4 + nt];
            #pragma unroll
            for (int j = 0; j < 4; j++) a[j] = __expf(a[j] * 10.0f);
            if (diag) {
                int cl = wn * 32 + nt * 8 + qc;
                #pragma unroll
                for (int h = 0; h < 2; h++) {
                    int rl = wm * 64 + mt * 16 + h * 8 + qr;
                    if (cl == rl)     a[h * 2 + 0] = 0.0f;
                    if (cl + 1 == rl) a[h * 2 + 1] = 0.0f;
                }
            }
        }

    // ---- primary fp16 stores + row sums ----
    #pragma unroll
    for (int mt = 0; mt < 4; mt++) {
        #pragma unroll
        for (int h = 0; h < 2; h++) {
            int rloc = wm * 64 + mt * 16 + h * 8 + qr;
            int grow = ti * 128 + rloc;
            __half* rowp = g_stage + (size_t)grow * OCOLS + colP;
            float rsum = 0.0f;
            #pragma unroll
            for (int nt = 0; nt < 4; nt++) {
                int cloc = wn * 32 + nt * 8 + qc;
                const float* a = acc[mt * 4 + nt];
                float v0 = a[h * 2 + 0], v1 = a[h * 2 + 1];
                rsum += v0 + v1;
                *(__half2*)(rowp + cloc) = __floats2half2_rn(v0, v1);
            }
            rsum += __shfl_xor_sync(0xffffffffu, rsum, 1);
            rsum += __shfl_xor_sync(0xffffffffu, rsum, 2);
            if ((lane & 3) == 0) atomicAdd(&rs_s[rloc], rsum);
        }
    }

    // ---- column sums (for transposed rows) ----
    #pragma unroll
    for (int nt = 0; nt < 4; nt++) {
        float c0s = 0.0f, c1s = 0.0f;
        #pragma unroll
        for (int mt = 0; mt < 4; mt++) {
            const float* a = acc[mt * 4 + nt];
            c0s += a[0] + a[2];
            c1s += a[1] + a[3];
        }
        #pragma unroll
        for (int o = 4; o <= 16; o <<= 1) {
            c0s += __shfl_xor_sync(0xffffffffu, c0s, o);
            c1s += __shfl_xor_sync(0xffffffffu, c1s, o);
        }
        if (lane < 4) {
            int cloc = wn * 32 + nt * 8 + qc;
            atomicAdd(&cs_s[cloc], c0s);
            atomicAdd(&cs_s[cloc + 1], c1s);
        }
    }

    // ---- stage transposed tile as packed half2: stg[(c>>1)*136 + r] ----
    if (doT) {
        uint32_t* stg = (uint32_t*)smem;
        #pragma unroll
        for (int mt = 0; mt < 4; mt++)
            #pragma unroll
            for (int nt = 0; nt < 4; nt++) {
                const float* a = acc[mt * 4 + nt];
                int cp = (wn * 32 + nt * 8 + qc) >> 1;   // col-pair index
                #pragma unroll
                for (int h = 0; h < 2; h++) {
                    int rloc = wm * 64 + mt * 16 + h * 8 + qr;
                    __half2 hv = __floats2half2_rn(a[h * 2 + 0], a[h * 2 + 1]);
                    stg[cp * TSTRIDE + rloc] = *reinterpret_cast<uint32_t*>(&hv);
                }
            }
    }
    __syncthreads();

    // ---- transposed coalesced fp16 writes (split low/high halves) ----
    if (doT) {
        const uint32_t* stg = (const uint32_t*)smem;
        #pragma unroll
        for (int rr = 0; rr < 8; rr++) {
            int cp = wid * 8 + rr;                        // 0..63
            uint4 q = *(const uint4*)(stg + cp * TSTRIDE + lane * 4);
            uint32_t l0 = __byte_perm(q.x, q.y, 0x5410);
            uint32_t l1 = __byte_perm(q.z, q.w, 0x5410);
            uint32_t h0 = __byte_perm(q.x, q.y, 0x7632);
            uint32_t h1 = __byte_perm(q.z, q.w, 0x7632);
            size_t base = (size_t)(tj * 128 + 2 * cp) * OCOLS + colT + lane * 4;
            *(uint2*)(g_stage + base)         = make_uint2(l0, l1);
            *(uint2*)(g_stage + base + OCOLS) = make_uint2(h0, h1);
        }
    }

    // ---- global sum accumulation ----
    if (tid < 128) {
        atomicAdd(&g_sums[sumP + ti * 128 + tid], rs_s[tid]);
        if (doT) atomicAdd(&g_sums[sumT + tj * 128 + tid], cs_s[tid]);
    }
}

// ---------------- scale pass: out = fp16_stage * (1/rowsum) ----------------
__global__ void scale_kernel(float4* __restrict__ out) {
    int idx = blockIdx.x * 256 + threadIdx.x;   // float4 index, 16M total
    int row = idx >> 12;                        // 4096 f4 per row
    int c4  = idx & 4095;
    float s = (c4 < 2048) ? g_sums[row] : g_sums[NROWS + row];
    float inv = __frcp_rn(s);
    uint2 st = *(const uint2*)(g_stage + (size_t)idx * 4);
    __half2 p0 = *reinterpret_cast<__half2*>(&st.x);
    __half2 p1 = *reinterpret_cast<__half2*>(&st.y);
    float2 f0 = __half22float2(p0);
    float2 f1 = __half22float2(p1);
    out[idx] = make_float4(f0.x * inv, f0.y * inv, f1.x * inv, f1.y * inv);
}

extern "C" void kernel_launch(void* const* d_in, const int* in_sizes, int n_in,
                              void* d_out, int out_size) {
    const float* z1 = (const float*)d_in[0];
    const float* z2 = (const float*)d_in[1];
    float* out = (float*)d_out;

    cudaFuncSetAttribute(gemm_exp_kernel,
                         cudaFuncAttributeMaxDynamicSharedMemorySize, SM_TOTAL);

    norm_kernel<<<2 * NROWS, 128>>>(z1, z2);
    gemm_exp_kernel<<<2080, 256, SM_TOTAL>>>();
    scale_kernel<<<(NROWS * OCOLS / 4) / 256, 256>>>(reinterpret_cast<float4*>(out));
}